// round 5
// baseline (speedup 1.0000x reference)
#include <cuda_runtime.h>

// ---------------------------------------------------------------------------
// TextLSTM: 2-layer LSTM (B=2048, T=256, EMB=128, NH=256) + output projection
// to 32000 classes. Per-CTA batch-slice design: each CTA owns 16 batch rows
// and runs all 256 timesteps locally (recurrence is per-row -> no inter-CTA
// sync needed). fp32 with packed fma.rn.f32x2 (FFMA2) inner products.
// ---------------------------------------------------------------------------

#define T_STEPS 256
#define B_SIZE  2048
#define EMB     128
#define NHID    256
#define NCLASS  32000
#define BR      16          // batch rows per CTA
#define NP      (BR/2)      // f32x2 row-pairs
#define NCTA    (B_SIZE/BR) // 128

typedef unsigned long long ull;

// Packed weights: W1[k][g*256+j], k in [0,128)=U_*1 (x part), [128,384)=V_*1 (h1)
//                 W2[k][g*256+j], k in [0,256)=U_*2 (h1n),   [256,512)=V_*2 (h2)
// gate order g: 0=i, 1=f, 2=c(g), 3=o
__device__ float g_W1[384 * 1024];
__device__ float g_W2[512 * 1024];
__device__ float g_h2f[B_SIZE * NHID];

// ---------------- packed f32x2 helpers ----------------
__device__ __forceinline__ void fma2(ull& acc, ull a, ull w) {
    asm("fma.rn.f32x2 %0, %1, %2, %0;" : "+l"(acc) : "l"(a), "l"(w));
}
__device__ __forceinline__ ull dup2(float w) {
    ull r; asm("mov.b64 %0, {%1, %1};" : "=l"(r) : "f"(w)); return r;
}
__device__ __forceinline__ float2 unpk(ull v) {
    float2 r; asm("mov.b64 {%0, %1}, %2;" : "=f"(r.x), "=f"(r.y) : "l"(v)); return r;
}
__device__ __forceinline__ float sigf(float x)   { return 1.0f / (1.0f + __expf(-x)); }
__device__ __forceinline__ float tanhf_(float x) { return 2.0f / (1.0f + __expf(-2.0f * x)) - 1.0f; }

// ---------------- weight packing ----------------
__global__ void pack_kernel(
    const float* __restrict__ Ui1, const float* __restrict__ Vi1,
    const float* __restrict__ Uf1, const float* __restrict__ Vf1,
    const float* __restrict__ Uc1, const float* __restrict__ Vc1,
    const float* __restrict__ Uo1, const float* __restrict__ Vo1,
    const float* __restrict__ Ui2, const float* __restrict__ Vi2,
    const float* __restrict__ Uf2, const float* __restrict__ Vf2,
    const float* __restrict__ Uc2, const float* __restrict__ Vc2,
    const float* __restrict__ Uo2, const float* __restrict__ Vo2)
{
    int i = blockIdx.x * blockDim.x + threadIdx.x;
    if (i < 384 * 1024) {
        int k = i >> 10, col = i & 1023;
        int g = col >> 8, j = col & 255;
        const float* U = (g == 0) ? Ui1 : (g == 1) ? Uf1 : (g == 2) ? Uc1 : Uo1;
        const float* V = (g == 0) ? Vi1 : (g == 1) ? Vf1 : (g == 2) ? Vc1 : Vo1;
        g_W1[i] = (k < EMB) ? U[k * NHID + j] : V[(k - EMB) * NHID + j];
    }
    if (i < 512 * 1024) {
        int k = i >> 10, col = i & 1023;
        int g = col >> 8, j = col & 255;
        const float* U = (g == 0) ? Ui2 : (g == 1) ? Uf2 : (g == 2) ? Uc2 : Uo2;
        const float* V = (g == 0) ? Vi2 : (g == 1) ? Vf2 : (g == 2) ? Vc2 : Vo2;
        g_W2[i] = (k < NHID) ? U[k * NHID + j] : V[(k - NHID) * NHID + j];
    }
}

// ---------------- inner-product accumulation ----------------
// acc[g][p] += sum_k S[k][2p..2p+1] * w[k*1024 + g*256]   (thread owns column j
// via the pointer offset baked into w). A-operand is warp-broadcast LDS.64.
template <int NK>
__device__ __forceinline__ void accum(ull acc[4][NP],
                                      const float* __restrict__ S,
                                      const float* __restrict__ w)
{
#pragma unroll 4
    for (int k = 0; k < NK; ++k) {
        ull w0 = dup2(w[k * 1024 + 0]);
        ull w1 = dup2(w[k * 1024 + 256]);
        ull w2 = dup2(w[k * 1024 + 512]);
        ull w3 = dup2(w[k * 1024 + 768]);
        const ull* a = (const ull*)(S + k * BR);
#pragma unroll
        for (int p = 0; p < NP; ++p) {
            ull av = a[p];
            fma2(acc[0][p], av, w0);
            fma2(acc[1][p], av, w1);
            fma2(acc[2][p], av, w2);
            fma2(acc[3][p], av, w3);
        }
    }
}

// ---------------- main LSTM kernel ----------------
// 256 threads; thread j owns gate element j for all 4 gates and all 16 rows.
// c1/c2 state therefore lives entirely in this thread's registers.
__global__ __launch_bounds__(256, 1)
void lstm_kernel(const int* __restrict__ X, const float* __restrict__ C,
                 const float* __restrict__ b_i, const float* __restrict__ b_f,
                 const float* __restrict__ b_c, const float* __restrict__ b_o)
{
    __shared__ float shA[384 * BR];   // [k][r] : x_t (k<128) | h1 (k in [128,384))
    __shared__ float shH2[NHID * BR]; // [u][r] : h2 state
    __shared__ int   shIdx[BR];

    const int tid  = threadIdx.x;
    const int row0 = blockIdx.x * BR;

    // zero h1 / h2 state
    for (int i = tid; i < NHID * BR; i += 256) {
        shA[EMB * BR + i] = 0.0f;
        shH2[i] = 0.0f;
    }

    float c1[BR], c2[BR];
#pragma unroll
    for (int r = 0; r < BR; ++r) { c1[r] = 0.0f; c2[r] = 0.0f; }

    const float bi = b_i[tid], bf = b_f[tid], bc = b_c[tid], bo = b_o[tid];

    ull acc[4][NP];

    for (int t = 0; t < T_STEPS; ++t) {
        // --- gather x_t = C[X[:, t]] into shA[0..127][*] ---
        if (tid < BR) shIdx[tid] = X[(row0 + tid) * T_STEPS + t];
        __syncthreads();
        for (int i = tid; i < EMB * BR; i += 256) {
            int e = i & (EMB - 1), r = i >> 7;
            shA[e * BR + r] = C[shIdx[r] * EMB + e];
        }
        __syncthreads();

        // --- layer 1: gates = [x | h1] @ W1 ---
#pragma unroll
        for (int g = 0; g < 4; ++g)
#pragma unroll
            for (int p = 0; p < NP; ++p) acc[g][p] = 0ull;
        accum<384>(acc, shA, g_W1 + tid);

        float h1n[BR];
#pragma unroll
        for (int p = 0; p < NP; ++p) {
            float2 ai = unpk(acc[0][p]), af = unpk(acc[1][p]);
            float2 ag = unpk(acc[2][p]), ao = unpk(acc[3][p]);
            float iv = sigf(ai.x + bi), fv = sigf(af.x + bf);
            float gv = tanhf_(ag.x + bc), ov = sigf(ao.x + bo);
            c1[2 * p] = c1[2 * p] * fv + iv * gv;
            h1n[2 * p] = ov * tanhf_(c1[2 * p]);
            iv = sigf(ai.y + bi); fv = sigf(af.y + bf);
            gv = tanhf_(ag.y + bc); ov = sigf(ao.y + bo);
            c1[2 * p + 1] = c1[2 * p + 1] * fv + iv * gv;
            h1n[2 * p + 1] = ov * tanhf_(c1[2 * p + 1]);
        }
        __syncthreads();  // all reads of shA done
        {
            float4* dst = (float4*)(shA + (EMB + tid) * BR);
            dst[0] = make_float4(h1n[0],  h1n[1],  h1n[2],  h1n[3]);
            dst[1] = make_float4(h1n[4],  h1n[5],  h1n[6],  h1n[7]);
            dst[2] = make_float4(h1n[8],  h1n[9],  h1n[10], h1n[11]);
            dst[3] = make_float4(h1n[12], h1n[13], h1n[14], h1n[15]);
        }
        __syncthreads();

        // --- layer 2: gates = [h1n | h2] @ W2 (note: layer-1 biases reused) ---
#pragma unroll
        for (int g = 0; g < 4; ++g)
#pragma unroll
            for (int p = 0; p < NP; ++p) acc[g][p] = 0ull;
        accum<256>(acc, shA + EMB * BR, g_W2 + tid);
        accum<256>(acc, shH2, g_W2 + 256 * 1024 + tid);

        float h2n[BR];
#pragma unroll
        for (int p = 0; p < NP; ++p) {
            float2 ai = unpk(acc[0][p]), af = unpk(acc[1][p]);
            float2 ag = unpk(acc[2][p]), ao = unpk(acc[3][p]);
            float iv = sigf(ai.x + bi), fv = sigf(af.x + bf);
            float gv = tanhf_(ag.x + bc), ov = sigf(ao.x + bo);
            c2[2 * p] = c2[2 * p] * fv + iv * gv;
            h2n[2 * p] = ov * tanhf_(c2[2 * p]);
            iv = sigf(ai.y + bi); fv = sigf(af.y + bf);
            gv = tanhf_(ag.y + bc); ov = sigf(ao.y + bo);
            c2[2 * p + 1] = c2[2 * p + 1] * fv + iv * gv;
            h2n[2 * p + 1] = ov * tanhf_(c2[2 * p + 1]);
        }
        __syncthreads();  // all reads of shH2 done
        {
            float4* dst = (float4*)(shH2 + tid * BR);
            dst[0] = make_float4(h2n[0],  h2n[1],  h2n[2],  h2n[3]);
            dst[1] = make_float4(h2n[4],  h2n[5],  h2n[6],  h2n[7]);
            dst[2] = make_float4(h2n[8],  h2n[9],  h2n[10], h2n[11]);
            dst[3] = make_float4(h2n[12], h2n[13], h2n[14], h2n[15]);
        }
    }

    __syncthreads();
    // write final h2 to global, coalesced over u
    for (int i = tid; i < NHID * BR; i += 256) {
        int u = i & (NHID - 1), r = i >> 8;
        g_h2f[(row0 + r) * NHID + u] = shH2[u * BR + r];
    }
}

// ---------------- output projection: out = h2 @ W_out + b_out ----------------
#define OUT_ROWS 32
#define OUT_COLS 512   // 2 columns per thread

__global__ __launch_bounds__(256, 1)
void out_kernel(const float* __restrict__ Wo, const float* __restrict__ bo,
                float* __restrict__ out)
{
    __shared__ float hs[NHID * OUT_ROWS];  // [k][r], 32 KB

    const int tid  = threadIdx.x;
    const int row0 = blockIdx.x * OUT_ROWS;
    const int col0 = blockIdx.y * OUT_COLS;

    for (int i = tid; i < NHID * OUT_ROWS; i += 256) {
        int u = i & (NHID - 1), r = i >> 8;
        hs[u * OUT_ROWS + r] = g_h2f[(row0 + r) * NHID + u];
    }
    __syncthreads();

    const int  ca = col0 + tid;
    const int  cb = col0 + 256 + tid;
    const bool va = (ca < NCLASS), vb = (cb < NCLASS);

    ull acc0[OUT_ROWS / 2], acc1[OUT_ROWS / 2];
#pragma unroll
    for (int p = 0; p < OUT_ROWS / 2; ++p) { acc0[p] = 0ull; acc1[p] = 0ull; }

#pragma unroll 4
    for (int k = 0; k < NHID; ++k) {
        float wa = va ? Wo[k * NCLASS + ca] : 0.0f;
        float wb = vb ? Wo[k * NCLASS + cb] : 0.0f;
        ull wa2 = dup2(wa), wb2 = dup2(wb);
        const ull* a = (const ull*)(hs + k * OUT_ROWS);
#pragma unroll
        for (int p = 0; p < OUT_ROWS / 2; ++p) {
            ull av = a[p];
            fma2(acc0[p], av, wa2);
            fma2(acc1[p], av, wb2);
        }
    }

    const float ba = va ? bo[ca] : 0.0f;
    const float bb = vb ? bo[cb] : 0.0f;
#pragma unroll
    for (int p = 0; p < OUT_ROWS / 2; ++p) {
        float2 a0 = unpk(acc0[p]);
        float2 a1 = unpk(acc1[p]);
        if (va) {
            out[(row0 + 2 * p)     * NCLASS + ca] = a0.x + ba;
            out[(row0 + 2 * p + 1) * NCLASS + ca] = a0.y + ba;
        }
        if (vb) {
            out[(row0 + 2 * p)     * NCLASS + cb] = a1.x + bb;
            out[(row0 + 2 * p + 1) * NCLASS + cb] = a1.y + bb;
        }
    }
}

// ---------------- launch ----------------
extern "C" void kernel_launch(void* const* d_in, const int* in_sizes, int n_in,
                              void* d_out, int out_size)
{
    (void)in_sizes; (void)n_in; (void)out_size;

    const int*   X    = (const int*)  d_in[0];
    const float* C    = (const float*)d_in[1];
    const float* Ui1  = (const float*)d_in[2];
    const float* Vi1  = (const float*)d_in[3];
    const float* Ui2  = (const float*)d_in[4];
    const float* Vi2  = (const float*)d_in[5];
    const float* bi1  = (const float*)d_in[6];
    const float* Uf1  = (const float*)d_in[7];
    const float* Vf1  = (const float*)d_in[8];
    const float* Uf2  = (const float*)d_in[9];
    const float* Vf2  = (const float*)d_in[10];
    const float* bf1  = (const float*)d_in[11];
    const float* Uc1  = (const float*)d_in[12];
    const float* Vc1  = (const float*)d_in[13];
    const float* Uc2  = (const float*)d_in[14];
    const float* Vc2  = (const float*)d_in[15];
    const float* bc1  = (const float*)d_in[16];
    const float* Uo1  = (const float*)d_in[17];
    const float* Vo1  = (const float*)d_in[18];
    const float* Uo2  = (const float*)d_in[19];
    const float* Vo2  = (const float*)d_in[20];
    const float* bo1  = (const float*)d_in[21];
    const float* Wout = (const float*)d_in[22];
    const float* bout = (const float*)d_in[23];
    float*       out  = (float*)d_out;

    pack_kernel<<<(512 * 1024 + 255) / 256, 256>>>(
        Ui1, Vi1, Uf1, Vf1, Uc1, Vc1, Uo1, Vo1,
        Ui2, Vi2, Uf2, Vf2, Uc2, Vc2, Uo2, Vo2);

    lstm_kernel<<<NCTA, 256>>>(X, C, bi1, bf1, bc1, bo1);

    dim3 og(B_SIZE / OUT_ROWS, (NCLASS + OUT_COLS - 1) / OUT_COLS);
    out_kernel<<<og, 256>>>(Wout, bout, out);
}

// round 6
// speedup vs baseline: 1.3462x; 1.3462x over previous
#include <cuda_runtime.h>

// ---------------------------------------------------------------------------
// TextLSTM: 2-layer LSTM (B=2048, T=256, EMB=128, NH=256) + projection to
// 32000 classes. Per-CTA batch-slice: each of 128 CTAs owns 16 batch rows and
// runs all 256 timesteps locally (recurrence is per-row -> zero inter-CTA
// sync). fp32 with packed fma.rn.f32x2 inner products, gate-interleaved
// LDG.128 weights with explicit double-buffered prefetch.
// ---------------------------------------------------------------------------

#define T_STEPS 256
#define B_SIZE  2048
#define EMB     128
#define NHID    256
#define NCLASS  32000
#define BR      16          // batch rows per CTA
#define NP      (BR/2)      // f32x2 row-pairs
#define NCTA    (B_SIZE/BR) // 128

typedef unsigned long long ull;

// Gate-interleaved packed weights: W[k][j][g], g in {i,f,c,o}.
//   W1: k in [0,128)=U_*1 (x part), [128,384)=V_*1 (h1 part)
//   W2: k in [0,256)=U_*2 (h1n part), [256,512)=V_*2 (h2 part)
// +8 rows of padding so the software-pipeline tail prefetch stays in bounds.
__device__ float g_W1[(384 + 8) * 1024];
__device__ float g_W2[(512 + 8) * 1024];
__device__ float g_h2f[B_SIZE * NHID];
__device__ int   g_dummy;

// ---------------- packed f32x2 helpers ----------------
__device__ __forceinline__ void fma2(ull& acc, ull a, ull w) {
    asm("fma.rn.f32x2 %0, %1, %2, %0;" : "+l"(acc) : "l"(a), "l"(w));
}
__device__ __forceinline__ ull dup2(float w) {
    ull r; asm("mov.b64 %0, {%1, %1};" : "=l"(r) : "f"(w)); return r;
}
__device__ __forceinline__ float2 unpk(ull v) {
    float2 r; asm("mov.b64 {%0, %1}, %2;" : "=f"(r.x), "=f"(r.y) : "l"(v)); return r;
}
__device__ __forceinline__ float sigf(float x)   { return 1.0f / (1.0f + __expf(-x)); }
__device__ __forceinline__ float tanhf_(float x) { return 2.0f / (1.0f + __expf(-2.0f * x)) - 1.0f; }

// ---------------- weight packing ----------------
__global__ void pack_kernel(
    const float* __restrict__ Ui1, const float* __restrict__ Vi1,
    const float* __restrict__ Uf1, const float* __restrict__ Vf1,
    const float* __restrict__ Uc1, const float* __restrict__ Vc1,
    const float* __restrict__ Uo1, const float* __restrict__ Vo1,
    const float* __restrict__ Ui2, const float* __restrict__ Vi2,
    const float* __restrict__ Uf2, const float* __restrict__ Vf2,
    const float* __restrict__ Uc2, const float* __restrict__ Vc2,
    const float* __restrict__ Uo2, const float* __restrict__ Vo2)
{
    int i = blockIdx.x * blockDim.x + threadIdx.x;
    if (i < 384 * 1024) {
        int k = i >> 10, j = (i >> 2) & 255, g = i & 3;
        const float* U = (g == 0) ? Ui1 : (g == 1) ? Uf1 : (g == 2) ? Uc1 : Uo1;
        const float* V = (g == 0) ? Vi1 : (g == 1) ? Vf1 : (g == 2) ? Vc1 : Vo1;
        g_W1[i] = (k < EMB) ? U[k * NHID + j] : V[(k - EMB) * NHID + j];
    }
    if (i < 512 * 1024) {
        int k = i >> 10, j = (i >> 2) & 255, g = i & 3;
        const float* U = (g == 0) ? Ui2 : (g == 1) ? Uf2 : (g == 2) ? Uc2 : Uo2;
        const float* V = (g == 0) ? Vi2 : (g == 1) ? Vf2 : (g == 2) ? Vc2 : Vo2;
        g_W2[i] = (k < NHID) ? U[k * NHID + j] : V[(k - NHID) * NHID + j];
    }
}

// ---------------- inner-product accumulation ----------------
// acc[g][p] += sum_k S[k][2p..2p+1] * W[k][tid][g].
// A-operand: warp-broadcast LDS.128 (two row-pairs per load).
// Weights: one LDG.128 per k (4 gates), double-buffered 4-k blocks.
__device__ __forceinline__ void step4(ull acc[4][NP], const float* __restrict__ S,
                                      int k0, const float4* __restrict__ wb)
{
#pragma unroll
    for (int u = 0; u < 4; ++u) {
        float4 wv = wb[u];
        ull w0 = dup2(wv.x), w1 = dup2(wv.y), w2 = dup2(wv.z), w3 = dup2(wv.w);
        const ulonglong2* a = (const ulonglong2*)(S + (k0 + u) * BR);
#pragma unroll
        for (int q = 0; q < 4; ++q) {
            ulonglong2 av = a[q];
            fma2(acc[0][2 * q],     av.x, w0);
            fma2(acc[1][2 * q],     av.x, w1);
            fma2(acc[2][2 * q],     av.x, w2);
            fma2(acc[3][2 * q],     av.x, w3);
            fma2(acc[0][2 * q + 1], av.y, w0);
            fma2(acc[1][2 * q + 1], av.y, w1);
            fma2(acc[2][2 * q + 1], av.y, w2);
            fma2(acc[3][2 * q + 1], av.y, w3);
        }
    }
}

// w points at thread's column: element for row k is w[k * 256].
template <int NK>
__device__ __forceinline__ void accum(ull acc[4][NP], const float* __restrict__ S,
                                      const float4* __restrict__ w)
{
    float4 bufA[4], bufB[4];
#pragma unroll
    for (int u = 0; u < 4; ++u) bufA[u] = w[u * 256];

#pragma unroll 1
    for (int kb = 0; kb < NK / 8; ++kb) {
        int k0 = kb * 8;
#pragma unroll
        for (int u = 0; u < 4; ++u) bufB[u] = w[(k0 + 4 + u) * 256];
        step4(acc, S, k0, bufA);
#pragma unroll
        for (int u = 0; u < 4; ++u) bufA[u] = w[(k0 + 8 + u) * 256];  // padded OOB-safe
        step4(acc, S, k0 + 4, bufB);
    }
}

// ---------------- main LSTM kernel ----------------
// 256 threads; thread j owns gate element j (all 4 gates, all 16 rows).
// c1/c2 state lives entirely in this thread's registers.
__global__ __launch_bounds__(256, 1)
void lstm_kernel(const int* __restrict__ X, const float* __restrict__ C,
                 const float* __restrict__ b_i, const float* __restrict__ b_f,
                 const float* __restrict__ b_c, const float* __restrict__ b_o)
{
    // shA rows [k][r]: k<128: x_t | 128..383: h1 | 384..639: h2
    __shared__ __align__(16) float shA[640 * BR];   // 40 KB
    __shared__ int shX[BR * T_STEPS];               // 16 KB

    const int tid  = threadIdx.x;
    const int row0 = blockIdx.x * BR;

    // stage token indices (X rows are contiguous per CTA slice)
    for (int i = tid; i < BR * T_STEPS; i += 256)
        shX[i] = X[row0 * T_STEPS + i];

    // zero h1/h2 state
    for (int i = tid; i < 512 * BR; i += 256)
        shA[EMB * BR + i] = 0.0f;

    float c1[BR], c2[BR];
#pragma unroll
    for (int r = 0; r < BR; ++r) { c1[r] = 0.0f; c2[r] = 0.0f; }

    const float bi = b_i[tid], bf = b_f[tid], bc = b_c[tid], bo = b_o[tid];
    const float4* W1 = (const float4*)g_W1 + tid;
    const float4* W2 = (const float4*)g_W2 + tid;

    ull acc[4][NP];
    __syncthreads();

    for (int t = 0; t < T_STEPS; ++t) {
        // --- gather x_t = C[X[:, t]] into shA rows 0..127 ---
        for (int i = tid; i < EMB * BR; i += 256) {
            int e = i & (EMB - 1), r = i >> 7;
            shA[e * BR + r] = C[shX[r * T_STEPS + t] * EMB + e];
        }
        __syncthreads();  // (B) x ready

        // --- layer 1: gates = [x | h1] @ W1 ---
#pragma unroll
        for (int g = 0; g < 4; ++g)
#pragma unroll
            for (int p = 0; p < NP; ++p) acc[g][p] = 0ull;
        accum<384>(acc, shA, W1);

        float h1n[BR];
#pragma unroll
        for (int p = 0; p < NP; ++p) {
            float2 ai = unpk(acc[0][p]), af = unpk(acc[1][p]);
            float2 ag = unpk(acc[2][p]), ao = unpk(acc[3][p]);
            float iv = sigf(ai.x + bi), fv = sigf(af.x + bf);
            float gv = tanhf_(ag.x + bc), ov = sigf(ao.x + bo);
            c1[2 * p] = c1[2 * p] * fv + iv * gv;
            h1n[2 * p] = ov * tanhf_(c1[2 * p]);
            iv = sigf(ai.y + bi); fv = sigf(af.y + bf);
            gv = tanhf_(ag.y + bc); ov = sigf(ao.y + bo);
            c1[2 * p + 1] = c1[2 * p + 1] * fv + iv * gv;
            h1n[2 * p + 1] = ov * tanhf_(c1[2 * p + 1]);
        }
        __syncthreads();  // (C) all layer-1 reads of shA done
        {
            float4* dst = (float4*)(shA + (EMB + tid) * BR);
            dst[0] = make_float4(h1n[0],  h1n[1],  h1n[2],  h1n[3]);
            dst[1] = make_float4(h1n[4],  h1n[5],  h1n[6],  h1n[7]);
            dst[2] = make_float4(h1n[8],  h1n[9],  h1n[10], h1n[11]);
            dst[3] = make_float4(h1n[12], h1n[13], h1n[14], h1n[15]);
        }
        __syncthreads();  // (D) h1n ready

        // --- layer 2: gates = [h1n | h2] @ W2 (layer-1 biases reused per ref) ---
#pragma unroll
        for (int g = 0; g < 4; ++g)
#pragma unroll
            for (int p = 0; p < NP; ++p) acc[g][p] = 0ull;
        accum<512>(acc, shA + EMB * BR, W2);

        float h2n[BR];
#pragma unroll
        for (int p = 0; p < NP; ++p) {
            float2 ai = unpk(acc[0][p]), af = unpk(acc[1][p]);
            float2 ag = unpk(acc[2][p]), ao = unpk(acc[3][p]);
            float iv = sigf(ai.x + bi), fv = sigf(af.x + bf);
            float gv = tanhf_(ag.x + bc), ov = sigf(ao.x + bo);
            c2[2 * p] = c2[2 * p] * fv + iv * gv;
            h2n[2 * p] = ov * tanhf_(c2[2 * p]);
            iv = sigf(ai.y + bi); fv = sigf(af.y + bf);
            gv = tanhf_(ag.y + bc); ov = sigf(ao.y + bo);
            c2[2 * p + 1] = c2[2 * p + 1] * fv + iv * gv;
            h2n[2 * p + 1] = ov * tanhf_(c2[2 * p + 1]);
        }
        __syncthreads();  // (E) all layer-2 reads of h2 done
        {
            float4* dst = (float4*)(shA + (384 + tid) * BR);
            dst[0] = make_float4(h2n[0],  h2n[1],  h2n[2],  h2n[3]);
            dst[1] = make_float4(h2n[4],  h2n[5],  h2n[6],  h2n[7]);
            dst[2] = make_float4(h2n[8],  h2n[9],  h2n[10], h2n[11]);
            dst[3] = make_float4(h2n[12], h2n[13], h2n[14], h2n[15]);
        }
        // next iteration's gather writes x rows (last read pre-C) and B/C/D
        // separate this h2 write from its layer-2 readers: safe without a bar.
    }

    __syncthreads();
    // final h2 -> global, coalesced over u
    for (int i = tid; i < NHID * BR; i += 256) {
        int u = i & (NHID - 1), r = i >> 8;
        g_h2f[(row0 + r) * NHID + u] = shA[(384 + u) * BR + r];
    }
}

// ---------------- output projection: out = h2 @ W_out + b_out ----------------
#define OUT_ROWS 32
#define OUT_COLS 512   // 2 columns per thread

__global__ __launch_bounds__(256, 1)
void out_kernel(const float* __restrict__ Wo, const float* __restrict__ bo,
                float* __restrict__ out)
{
    __shared__ __align__(16) float hs[NHID * OUT_ROWS];  // [k][r], 32 KB

    const int tid  = threadIdx.x;
    const int row0 = blockIdx.x * OUT_ROWS;
    const int col0 = blockIdx.y * OUT_COLS;

    for (int i = tid; i < NHID * OUT_ROWS; i += 256) {
        int u = i & (NHID - 1), r = i >> 8;
        hs[u * OUT_ROWS + r] = g_h2f[(row0 + r) * NHID + u];
    }
    __syncthreads();

    const int  ca = col0 + tid;
    const int  cb = col0 + 256 + tid;
    const bool va = (ca < NCLASS), vb = (cb < NCLASS);

    ull acc0[OUT_ROWS / 2], acc1[OUT_ROWS / 2];
#pragma unroll
    for (int p = 0; p < OUT_ROWS / 2; ++p) { acc0[p] = 0ull; acc1[p] = 0ull; }

#pragma unroll 4
    for (int k = 0; k < NHID; ++k) {
        float wa = va ? Wo[k * NCLASS + ca] : 0.0f;
        float wb = vb ? Wo[k * NCLASS + cb] : 0.0f;
        ull wa2 = dup2(wa), wb2 = dup2(wb);
        const ull* a = (const ull*)(hs + k * OUT_ROWS);
#pragma unroll
        for (int p = 0; p < OUT_ROWS / 2; ++p) {
            ull av = a[p];
            fma2(acc0[p], av, wa2);
            fma2(acc1[p], av, wb2);
        }
    }

    const float ba = va ? bo[ca] : 0.0f;
    const float bb = vb ? bo[cb] : 0.0f;
#pragma unroll
    for (int p = 0; p < OUT_ROWS / 2; ++p) {
        float2 a0 = unpk(acc0[p]);
        float2 a1 = unpk(acc1[p]);
        if (va) {
            out[(row0 + 2 * p)     * NCLASS + ca] = a0.x + ba;
            out[(row0 + 2 * p + 1) * NCLASS + ca] = a0.y + ba;
        }
        if (vb) {
            out[(row0 + 2 * p)     * NCLASS + cb] = a1.x + bb;
            out[(row0 + 2 * p + 1) * NCLASS + cb] = a1.y + bb;
        }
    }
}

// Trailing no-op kernel: pads the launch sequence to 4 per call so ncu's
// fixed "-s 5" lands on lstm_kernel (launch index 5 = 2nd call's lstm).
__global__ void pad_kernel() {
    if (threadIdx.x == 0 && blockIdx.x == 0) g_dummy = 1;
}

// ---------------- launch ----------------
extern "C" void kernel_launch(void* const* d_in, const int* in_sizes, int n_in,
                              void* d_out, int out_size)
{
    (void)in_sizes; (void)n_in; (void)out_size;

    const int*   X    = (const int*)  d_in[0];
    const float* C    = (const float*)d_in[1];
    const float* Ui1  = (const float*)d_in[2];
    const float* Vi1  = (const float*)d_in[3];
    const float* Ui2  = (const float*)d_in[4];
    const float* Vi2  = (const float*)d_in[5];
    const float* bi1  = (const float*)d_in[6];
    const float* Uf1  = (const float*)d_in[7];
    const float* Vf1  = (const float*)d_in[8];
    const float* Uf2  = (const float*)d_in[9];
    const float* Vf2  = (const float*)d_in[10];
    const float* bf1  = (const float*)d_in[11];
    const float* Uc1  = (const float*)d_in[12];
    const float* Vc1  = (const float*)d_in[13];
    const float* Uc2  = (const float*)d_in[14];
    const float* Vc2  = (const float*)d_in[15];
    const float* bc1  = (const float*)d_in[16];
    const float* Uo1  = (const float*)d_in[17];
    const float* Vo1  = (const float*)d_in[18];
    const float* Uo2  = (const float*)d_in[19];
    const float* Vo2  = (const float*)d_in[20];
    const float* bo1  = (const float*)d_in[21];
    const float* Wout = (const float*)d_in[22];
    const float* bout = (const float*)d_in[23];
    float*       out  = (float*)d_out;

    pack_kernel<<<(512 * 1024 + 255) / 256, 256>>>(
        Ui1, Vi1, Uf1, Vf1, Uc1, Vc1, Uo1, Vo1,
        Ui2, Vi2, Uf2, Vf2, Uc2, Vc2, Uo2, Vo2);

    lstm_kernel<<<NCTA, 256>>>(X, C, bi1, bf1, bc1, bo1);

    dim3 og(B_SIZE / OUT_ROWS, (NCLASS + OUT_COLS - 1) / OUT_COLS);
    out_kernel<<<og, 256>>>(Wout, bout, out);

    pad_kernel<<<1, 32>>>();
}

// round 8
// speedup vs baseline: 1.3470x; 1.0006x over previous
#include <cuda_runtime.h>

// ---------------------------------------------------------------------------
// TextLSTM: 2-layer LSTM (B=2048, T=256, EMB=128, NH=256) + projection to
// 32000 classes. Per-CTA batch-slice: each of 128 CTAs owns 16 batch rows and
// runs all 256 timesteps locally (recurrence is per-row -> zero inter-CTA
// sync). fp32 with packed fma.rn.f32x2 inner products, gate-interleaved
// LDG.128 weights with explicit double-buffered prefetch.
// ---------------------------------------------------------------------------

#define T_STEPS 256
#define B_SIZE  2048
#define EMB     128
#define NHID    256
#define NCLASS  32000
#define BR      16          // batch rows per CTA
#define NP      (BR/2)      // f32x2 row-pairs
#define NCTA    (B_SIZE/BR) // 128

typedef unsigned long long ull;

// Gate-interleaved packed weights: W[k][j][g], g in {i,f,c,o}.
//   W1: k in [0,128)=U_*1 (x part), [128,384)=V_*1 (h1 part)
//   W2: k in [0,256)=U_*2 (h1n part), [256,512)=V_*2 (h2 part)
// +8 rows of padding so the software-pipeline tail prefetch stays in bounds.
__device__ float g_W1[(384 + 8) * 1024];
__device__ float g_W2[(512 + 8) * 1024];
__device__ float g_h2f[B_SIZE * NHID];
__device__ int   g_dummy;

// ---------------- packed f32x2 helpers ----------------
__device__ __forceinline__ void fma2(ull& acc, ull a, ull w) {
    asm("fma.rn.f32x2 %0, %1, %2, %0;" : "+l"(acc) : "l"(a), "l"(w));
}
__device__ __forceinline__ ull dup2(float w) {
    ull r; asm("mov.b64 %0, {%1, %1};" : "=l"(r) : "f"(w)); return r;
}
__device__ __forceinline__ float2 unpk(ull v) {
    float2 r; asm("mov.b64 {%0, %1}, %2;" : "=f"(r.x), "=f"(r.y) : "l"(v)); return r;
}
__device__ __forceinline__ float sigf(float x)   { return 1.0f / (1.0f + __expf(-x)); }
__device__ __forceinline__ float tanhf_(float x) { return 2.0f / (1.0f + __expf(-2.0f * x)) - 1.0f; }

// ---------------- weight packing ----------------
__global__ void pack_kernel(
    const float* __restrict__ Ui1, const float* __restrict__ Vi1,
    const float* __restrict__ Uf1, const float* __restrict__ Vf1,
    const float* __restrict__ Uc1, const float* __restrict__ Vc1,
    const float* __restrict__ Uo1, const float* __restrict__ Vo1,
    const float* __restrict__ Ui2, const float* __restrict__ Vi2,
    const float* __restrict__ Uf2, const float* __restrict__ Vf2,
    const float* __restrict__ Uc2, const float* __restrict__ Vc2,
    const float* __restrict__ Uo2, const float* __restrict__ Vo2)
{
    int i = blockIdx.x * blockDim.x + threadIdx.x;
    if (i < 384 * 1024) {
        int k = i >> 10, j = (i >> 2) & 255, g = i & 3;
        const float* U = (g == 0) ? Ui1 : (g == 1) ? Uf1 : (g == 2) ? Uc1 : Uo1;
        const float* V = (g == 0) ? Vi1 : (g == 1) ? Vf1 : (g == 2) ? Vc1 : Vo1;
        g_W1[i] = (k < EMB) ? U[k * NHID + j] : V[(k - EMB) * NHID + j];
    }
    if (i < 512 * 1024) {
        int k = i >> 10, j = (i >> 2) & 255, g = i & 3;
        const float* U = (g == 0) ? Ui2 : (g == 1) ? Uf2 : (g == 2) ? Uc2 : Uo2;
        const float* V = (g == 0) ? Vi2 : (g == 1) ? Vf2 : (g == 2) ? Vc2 : Vo2;
        g_W2[i] = (k < NHID) ? U[k * NHID + j] : V[(k - NHID) * NHID + j];
    }
}

// ---------------- inner-product accumulation ----------------
// acc[g][p] += sum_k S[k][2p..2p+1] * W[k][tid][g].
// A-operand: warp-broadcast LDS.128 (two row-pairs per load).
// Weights: one LDG.128 per k (4 gates), double-buffered 4-k blocks.
__device__ __forceinline__ void step4(ull acc[4][NP], const float* __restrict__ S,
                                      int k0, const float4* __restrict__ wb)
{
#pragma unroll
    for (int u = 0; u < 4; ++u) {
        float4 wv = wb[u];
        ull w0 = dup2(wv.x), w1 = dup2(wv.y), w2 = dup2(wv.z), w3 = dup2(wv.w);
        const ulonglong2* a = (const ulonglong2*)(S + (k0 + u) * BR);
#pragma unroll
        for (int q = 0; q < 4; ++q) {
            ulonglong2 av = a[q];
            fma2(acc[0][2 * q],     av.x, w0);
            fma2(acc[1][2 * q],     av.x, w1);
            fma2(acc[2][2 * q],     av.x, w2);
            fma2(acc[3][2 * q],     av.x, w3);
            fma2(acc[0][2 * q + 1], av.y, w0);
            fma2(acc[1][2 * q + 1], av.y, w1);
            fma2(acc[2][2 * q + 1], av.y, w2);
            fma2(acc[3][2 * q + 1], av.y, w3);
        }
    }
}

// w points at thread's column: element for row k is w[k * 256].
template <int NK>
__device__ __forceinline__ void accum(ull acc[4][NP], const float* __restrict__ S,
                                      const float4* __restrict__ w)
{
    float4 bufA[4], bufB[4];
#pragma unroll
    for (int u = 0; u < 4; ++u) bufA[u] = w[u * 256];

#pragma unroll 1
    for (int kb = 0; kb < NK / 8; ++kb) {
        int k0 = kb * 8;
#pragma unroll
        for (int u = 0; u < 4; ++u) bufB[u] = w[(k0 + 4 + u) * 256];
        step4(acc, S, k0, bufA);
#pragma unroll
        for (int u = 0; u < 4; ++u) bufA[u] = w[(k0 + 8 + u) * 256];  // padded OOB-safe
        step4(acc, S, k0 + 4, bufB);
    }
}

// ---------------- main LSTM kernel ----------------
// 256 threads; thread j owns gate element j (all 4 gates, all 16 rows).
// c1/c2 state lives entirely in this thread's registers.
__global__ __launch_bounds__(256, 1)
void lstm_kernel(const int* __restrict__ X, const float* __restrict__ C,
                 const float* __restrict__ b_i, const float* __restrict__ b_f,
                 const float* __restrict__ b_c, const float* __restrict__ b_o)
{
    // shA rows [k][r]: k<128: x_t | 128..383: h1 | 384..639: h2
    __shared__ __align__(16) float shA[640 * BR];   // 40 KB
    __shared__ int shX[BR * T_STEPS];               // 16 KB

    const int tid  = threadIdx.x;
    const int row0 = blockIdx.x * BR;

    // stage token indices (X rows are contiguous per CTA slice)
    for (int i = tid; i < BR * T_STEPS; i += 256)
        shX[i] = X[row0 * T_STEPS + i];

    // zero h1/h2 state
    for (int i = tid; i < 512 * BR; i += 256)
        shA[EMB * BR + i] = 0.0f;

    float c1[BR], c2[BR];
#pragma unroll
    for (int r = 0; r < BR; ++r) { c1[r] = 0.0f; c2[r] = 0.0f; }

    const float bi = b_i[tid], bf = b_f[tid], bc = b_c[tid], bo = b_o[tid];
    const float4* W1 = (const float4*)g_W1 + tid;
    const float4* W2 = (const float4*)g_W2 + tid;

    ull acc[4][NP];
    __syncthreads();

    for (int t = 0; t < T_STEPS; ++t) {
        // --- gather x_t = C[X[:, t]] into shA rows 0..127 ---
        for (int i = tid; i < EMB * BR; i += 256) {
            int e = i & (EMB - 1), r = i >> 7;
            shA[e * BR + r] = C[shX[r * T_STEPS + t] * EMB + e];
        }
        __syncthreads();  // (B) x ready

        // --- layer 1: gates = [x | h1] @ W1 ---
#pragma unroll
        for (int g = 0; g < 4; ++g)
#pragma unroll
            for (int p = 0; p < NP; ++p) acc[g][p] = 0ull;
        accum<384>(acc, shA, W1);

        float h1n[BR];
#pragma unroll
        for (int p = 0; p < NP; ++p) {
            float2 ai = unpk(acc[0][p]), af = unpk(acc[1][p]);
            float2 ag = unpk(acc[2][p]), ao = unpk(acc[3][p]);
            float iv = sigf(ai.x + bi), fv = sigf(af.x + bf);
            float gv = tanhf_(ag.x + bc), ov = sigf(ao.x + bo);
            c1[2 * p] = c1[2 * p] * fv + iv * gv;
            h1n[2 * p] = ov * tanhf_(c1[2 * p]);
            iv = sigf(ai.y + bi); fv = sigf(af.y + bf);
            gv = tanhf_(ag.y + bc); ov = sigf(ao.y + bo);
            c1[2 * p + 1] = c1[2 * p + 1] * fv + iv * gv;
            h1n[2 * p + 1] = ov * tanhf_(c1[2 * p + 1]);
        }
        __syncthreads();  // (C) all layer-1 reads of shA done
        {
            float4* dst = (float4*)(shA + (EMB + tid) * BR);
            dst[0] = make_float4(h1n[0],  h1n[1],  h1n[2],  h1n[3]);
            dst[1] = make_float4(h1n[4],  h1n[5],  h1n[6],  h1n[7]);
            dst[2] = make_float4(h1n[8],  h1n[9],  h1n[10], h1n[11]);
            dst[3] = make_float4(h1n[12], h1n[13], h1n[14], h1n[15]);
        }
        __syncthreads();  // (D) h1n ready

        // --- layer 2: gates = [h1n | h2] @ W2 (layer-1 biases reused per ref) ---
#pragma unroll
        for (int g = 0; g < 4; ++g)
#pragma unroll
            for (int p = 0; p < NP; ++p) acc[g][p] = 0ull;
        accum<512>(acc, shA + EMB * BR, W2);

        float h2n[BR];
#pragma unroll
        for (int p = 0; p < NP; ++p) {
            float2 ai = unpk(acc[0][p]), af = unpk(acc[1][p]);
            float2 ag = unpk(acc[2][p]), ao = unpk(acc[3][p]);
            float iv = sigf(ai.x + bi), fv = sigf(af.x + bf);
            float gv = tanhf_(ag.x + bc), ov = sigf(ao.x + bo);
            c2[2 * p] = c2[2 * p] * fv + iv * gv;
            h2n[2 * p] = ov * tanhf_(c2[2 * p]);
            iv = sigf(ai.y + bi); fv = sigf(af.y + bf);
            gv = tanhf_(ag.y + bc); ov = sigf(ao.y + bo);
            c2[2 * p + 1] = c2[2 * p + 1] * fv + iv * gv;
            h2n[2 * p + 1] = ov * tanhf_(c2[2 * p + 1]);
        }
        __syncthreads();  // (E) all layer-2 reads of h2 done
        {
            float4* dst = (float4*)(shA + (384 + tid) * BR);
            dst[0] = make_float4(h2n[0],  h2n[1],  h2n[2],  h2n[3]);
            dst[1] = make_float4(h2n[4],  h2n[5],  h2n[6],  h2n[7]);
            dst[2] = make_float4(h2n[8],  h2n[9],  h2n[10], h2n[11]);
            dst[3] = make_float4(h2n[12], h2n[13], h2n[14], h2n[15]);
        }
        // next iteration's gather writes x rows (last read pre-C) and B/C/D
        // separate this h2 write from its layer-2 readers: safe without a bar.
    }

    __syncthreads();
    // final h2 -> global, coalesced over u
    for (int i = tid; i < NHID * BR; i += 256) {
        int u = i & (NHID - 1), r = i >> 8;
        g_h2f[(row0 + r) * NHID + u] = shA[(384 + u) * BR + r];
    }
}

// ---------------- output projection: out = h2 @ W_out + b_out ----------------
#define OUT_ROWS 32
#define OUT_COLS 512   // 2 columns per thread

__global__ __launch_bounds__(256, 1)
void out_kernel(const float* __restrict__ Wo, const float* __restrict__ bo,
                float* __restrict__ out)
{
    __shared__ __align__(16) float hs[NHID * OUT_ROWS];  // [k][r], 32 KB

    const int tid  = threadIdx.x;
    const int row0 = blockIdx.x * OUT_ROWS;
    const int col0 = blockIdx.y * OUT_COLS;

    for (int i = tid; i < NHID * OUT_ROWS; i += 256) {
        int u = i & (NHID - 1), r = i >> 8;
        hs[u * OUT_ROWS + r] = g_h2f[(row0 + r) * NHID + u];
    }
    __syncthreads();

    const int  ca = col0 + tid;
    const int  cb = col0 + 256 + tid;
    const bool va = (ca < NCLASS), vb = (cb < NCLASS);

    ull acc0[OUT_ROWS / 2], acc1[OUT_ROWS / 2];
#pragma unroll
    for (int p = 0; p < OUT_ROWS / 2; ++p) { acc0[p] = 0ull; acc1[p] = 0ull; }

#pragma unroll 4
    for (int k = 0; k < NHID; ++k) {
        float wa = va ? Wo[k * NCLASS + ca] : 0.0f;
        float wb = vb ? Wo[k * NCLASS + cb] : 0.0f;
        ull wa2 = dup2(wa), wb2 = dup2(wb);
        const ull* a = (const ull*)(hs + k * OUT_ROWS);
#pragma unroll
        for (int p = 0; p < OUT_ROWS / 2; ++p) {
            ull av = a[p];
            fma2(acc0[p], av, wa2);
            fma2(acc1[p], av, wb2);
        }
    }

    const float ba = va ? bo[ca] : 0.0f;
    const float bb = vb ? bo[cb] : 0.0f;
#pragma unroll
    for (int p = 0; p < OUT_ROWS / 2; ++p) {
        float2 a0 = unpk(acc0[p]);
        float2 a1 = unpk(acc1[p]);
        if (va) {
            out[(row0 + 2 * p)     * NCLASS + ca] = a0.x + ba;
            out[(row0 + 2 * p + 1) * NCLASS + ca] = a0.y + ba;
        }
        if (vb) {
            out[(row0 + 2 * p)     * NCLASS + cb] = a1.x + bb;
            out[(row0 + 2 * p + 1) * NCLASS + cb] = a1.y + bb;
        }
    }
}

// Trailing no-op kernel: pads the launch sequence to 4 per call so ncu's
// fixed "-s 5" lands on lstm_kernel (launch index 5 = 2nd call's lstm).
__global__ void pad_kernel() {
    if (threadIdx.x == 0 && blockIdx.x == 0) g_dummy = 1;
}

// ---------------- launch ----------------
extern "C" void kernel_launch(void* const* d_in, const int* in_sizes, int n_in,
                              void* d_out, int out_size)
{
    (void)in_sizes; (void)n_in; (void)out_size;

    const int*   X    = (const int*)  d_in[0];
    const float* C    = (const float*)d_in[1];
    const float* Ui1  = (const float*)d_in[2];
    const float* Vi1  = (const float*)d_in[3];
    const float* Ui2  = (const float*)d_in[4];
    const float* Vi2  = (const float*)d_in[5];
    const float* bi1  = (const float*)d_in[6];
    const float* Uf1  = (const float*)d_in[7];
    const float* Vf1  = (const float*)d_in[8];
    const float* Uf2  = (const float*)d_in[9];
    const float* Vf2  = (const float*)d_in[10];
    const float* bf1  = (const float*)d_in[11];
    const float* Uc1  = (const float*)d_in[12];
    const float* Vc1  = (const float*)d_in[13];
    const float* Uc2  = (const float*)d_in[14];
    const float* Vc2  = (const float*)d_in[15];
    const float* bc1  = (const float*)d_in[16];
    const float* Uo1  = (const float*)d_in[17];
    const float* Vo1  = (const float*)d_in[18];
    const float* Uo2  = (const float*)d_in[19];
    const float* Vo2  = (const float*)d_in[20];
    const float* bo1  = (const float*)d_in[21];
    const float* Wout = (const float*)d_in[22];
    const float* bout = (const float*)d_in[23];
    float*       out  = (float*)d_out;

    pack_kernel<<<(512 * 1024 + 255) / 256, 256>>>(
        Ui1, Vi1, Uf1, Vf1, Uc1, Vc1, Uo1, Vo1,
        Ui2, Vi2, Uf2, Vf2, Uc2, Vc2, Uo2, Vo2);

    lstm_kernel<<<NCTA, 256>>>(X, C, bi1, bf1, bc1, bo1);

    dim3 og(B_SIZE / OUT_ROWS, (NCLASS + OUT_COLS - 1) / OUT_COLS);
    out_kernel<<<og, 256>>>(Wout, bout, out);

    pad_kernel<<<1, 32>>>();
}